// round 1
// baseline (speedup 1.0000x reference)
#include <cuda_runtime.h>
#include <cstdint>

// Decoder: 2-layer LSTM + Luong global attention.
// T=64 steps, B=64, S=64, H=E=1024, L=2, V=50000.
//
// Inputs (metadata order):
//  0 input  int32 [T,B]
//  1 h0     f32   [L,B,H]
//  2 c0     f32   [L,B,H]
//  3 context f32  [S,B,H]
//  4 emb    f32   [V,E]
//  5 w_ih   f32   [L,4H,H]
//  6 w_hh   f32   [L,4H,H]
//  7 b_ih   f32   [L,4H]
//  8 b_hh   f32   [L,4H]
//  9 w_in   f32   [H,H]
// 10 w_out  f32   [H,2H]
// Output: concat(outs [T,B,H], h_f [L,B,H], c_f [L,B,H], attn_last [B,S])

#define TT 64
#define BB 64
#define SS 64
#define HH 1024
#define LL 2

typedef unsigned long long ull;

// ---------- packed fp32x2 helpers (sm_103a FFMA2 path) ----------
__device__ __forceinline__ void fma2(ull &d, ull a, ull b) {
    asm volatile("fma.rn.f32x2 %0, %1, %2, %0;" : "+l"(d) : "l"(a), "l"(b));
}
__device__ __forceinline__ ull dup2(float x) {
    unsigned u = __float_as_uint(x);
    return ((ull)u << 32) | (ull)u;
}
__device__ __forceinline__ float2 unpk(ull v) {
    float2 f;
    f.x = __uint_as_float((unsigned)v);
    f.y = __uint_as_float((unsigned)(v >> 32));
    return f;
}
__device__ __forceinline__ float sigm_(float x) { return 1.f / (1.f + expf(-x)); }

// ---------- scratch (static device globals; no runtime allocation) ----------
__device__ float g_X0[(size_t)TT * BB * 4 * HH];   // precomputed x@w_ih0^T + biases, [T*B, 4H]
__device__ float g_hbuf[2][LL * BB * HH];          // ping-pong h state
__device__ float g_c[LL * BB * HH];                // c state (in-place)
__device__ float g_q[BB * HH];
__device__ float g_wc[BB * HH];
__device__ float g_attn[BB * SS];

// =====================================================================
// GEMM: C[M,N] = A1[M,1024] @ W1[N,1024-row]^T (+ A2 @ W2^T) (+addC) (+bias) (+act)
// Tile 64(M) x 32(N), BK=16, 256 threads, 4x2 micro-tile as f32x2 pairs.
// EPI: 0 = store (opt bias), 1 = store tanh, 2 = fused LSTM cell.
// In EPI==2 the block's 32 local cols map to the 4 gates (i,f,g,o) of
// 8 hidden units: col_local -> gate = col>>3, j = blockIdx.x*8 + (col&7),
// W row = gate*H + j. Epilogue computes c,h for those 8 j across all 64 b.
// =====================================================================
template <int EPI, bool GATHER, bool PAIR2>
__global__ __launch_bounds__(256) void gemm_k(
    const float* __restrict__ A1, const float* __restrict__ W1,
    const float* __restrict__ A2, const float* __restrict__ W2,
    int ldW,
    const int* __restrict__ gidx,
    const float* __restrict__ addC,                 // [B,4H] (EPI==2 only)
    const float* __restrict__ bias1, const float* __restrict__ bias2,
    float* __restrict__ C, int ldC,                 // EPI 0/1
    float* __restrict__ cSt, float* __restrict__ hOut)  // EPI 2
{
    __shared__ __align__(16) float As[16][68];  // padded for bank conflicts
    __shared__ __align__(16) ull   Wsd[16][34]; // W duplicated (w,w), padded
    __shared__ float Cs[32][64];                // LSTM epilogue staging

    const int tx = threadIdx.x;
    const int m0 = (tx >> 4) << 2;   // 0..60 step 4
    const int n0 = (tx & 15) << 1;   // 0..30 step 2

    const int arow  = tx >> 2;        // 0..63
    const int akoff = (tx & 3) << 2;  // 0,4,8,12
    const int wrl   = tx >> 3;        // 0..31
    const int wk    = (tx & 7) << 1;  // 0..14 step 2

    const int gm = blockIdx.y * 64 + arow;
    int wr;
    if (EPI == 2) wr = (wrl >> 3) * HH + blockIdx.x * 8 + (wrl & 7);
    else          wr = blockIdx.x * 32 + wrl;

    ull a00 = 0, a01 = 0, a10 = 0, a11 = 0;

    const int NKT = PAIR2 ? 128 : 64;
    for (int kt = 0; kt < NKT; ++kt) {
        const float* Ap = A1;
        const float* Wp = W1;
        int kk;
        if (PAIR2 && kt >= 64) { Ap = A2; Wp = W2; kk = (kt - 64) * 16; }
        else                   { kk = kt * 16; }

        const float* ar = GATHER ? (A1 + (size_t)gidx[gm] * 1024)
                                 : (Ap + (size_t)gm * 1024);
        float4 av = *(const float4*)(ar + kk + akoff);
        float2 wv = *(const float2*)(Wp + (size_t)wr * ldW + kk + wk);

        __syncthreads();
        As[akoff + 0][arow] = av.x;
        As[akoff + 1][arow] = av.y;
        As[akoff + 2][arow] = av.z;
        As[akoff + 3][arow] = av.w;
        Wsd[wk][wrl]     = dup2(wv.x);
        Wsd[wk + 1][wrl] = dup2(wv.y);
        __syncthreads();

#pragma unroll
        for (int k = 0; k < 16; ++k) {
            ulonglong2 aa = *(const ulonglong2*)&As[k][m0];   // rows (m0,m0+1),(m0+2,m0+3)
            ulonglong2 ww = *(const ulonglong2*)&Wsd[k][n0];  // cols n0, n0+1 (dup'd)
            fma2(a00, aa.x, ww.x);
            fma2(a10, aa.y, ww.x);
            fma2(a01, aa.x, ww.y);
            fma2(a11, aa.y, ww.y);
        }
    }

    if (EPI == 2) {
        __syncthreads();
        *(float2*)&Cs[n0][m0]         = unpk(a00);
        *(float2*)&Cs[n0][m0 + 2]     = unpk(a10);
        *(float2*)&Cs[n0 + 1][m0]     = unpk(a01);
        *(float2*)&Cs[n0 + 1][m0 + 2] = unpk(a11);
        __syncthreads();
#pragma unroll
        for (int e = tx; e < 512; e += 256) {
            int b = e & 63, jj = e >> 6;
            int colh = blockIdx.x * 8 + jj;
            float gi = Cs[jj][b];
            float gf = Cs[8 + jj][b];
            float gg = Cs[16 + jj][b];
            float go = Cs[24 + jj][b];
            if (addC) {
                const float* ac = addC + (size_t)b * 4096 + colh;
                gi += ac[0]; gf += ac[HH]; gg += ac[2 * HH]; go += ac[3 * HH];
            }
            if (bias1) {
                gi += bias1[colh] + bias2[colh];
                gf += bias1[HH + colh] + bias2[HH + colh];
                gg += bias1[2 * HH + colh] + bias2[2 * HH + colh];
                go += bias1[3 * HH + colh] + bias2[3 * HH + colh];
            }
            float ii = sigm_(gi), ff = sigm_(gf);
            float g = tanhf(gg), oo = sigm_(go);
            float c = ff * cSt[b * HH + colh] + ii * g;
            cSt[b * HH + colh] = c;
            hOut[b * HH + colh] = oo * tanhf(c);
        }
    } else {
        int colb = blockIdx.x * 32 + n0;
        int mb = blockIdx.y * 64 + m0;
        float bA0 = 0.f, bA1 = 0.f;
        if (bias1) {
            bA0 = bias1[colb] + bias2[colb];
            bA1 = bias1[colb + 1] + bias2[colb + 1];
        }
        float2 v00 = unpk(a00), v10 = unpk(a10), v01 = unpk(a01), v11 = unpk(a11);
        float r0[4] = {v00.x, v00.y, v10.x, v10.y};
        float r1[4] = {v01.x, v01.y, v11.x, v11.y};
#pragma unroll
        for (int dm = 0; dm < 4; ++dm) {
            float x0 = r0[dm] + bA0;
            float x1 = r1[dm] + bA1;
            if (EPI == 1) { x0 = tanhf(x0); x1 = tanhf(x1); }
            C[(size_t)(mb + dm) * ldC + colb]     = x0;
            C[(size_t)(mb + dm) * ldC + colb + 1] = x1;
        }
    }
}

// =====================================================================
// Attention: one block per batch b. scores -> softmax -> wc.
// ctx is original context [S,B,H]; scores[b,s] = <context[s,b,:], q[b,:]>.
// =====================================================================
__global__ __launch_bounds__(256) void attn_k(
    const float* __restrict__ q, const float* __restrict__ ctx,
    float* __restrict__ wc, float* __restrict__ attn)
{
    __shared__ float qs[HH];
    __shared__ float sc[SS];
    const int b = blockIdx.x;
    const int tx = threadIdx.x;

    *(float4*)&qs[tx * 4] = *(const float4*)&q[(size_t)b * HH + tx * 4];
    __syncthreads();

    const int wid = tx >> 5, lane = tx & 31;
    for (int s = wid; s < SS; s += 8) {
        const float* cp = ctx + ((size_t)s * BB + b) * HH;
        float acc = 0.f;
#pragma unroll
        for (int i = 0; i < 8; ++i) {
            float4 c4 = *(const float4*)(cp + i * 128 + lane * 4);
            float4 q4 = *(const float4*)&qs[i * 128 + lane * 4];
            acc += c4.x * q4.x + c4.y * q4.y + c4.z * q4.z + c4.w * q4.w;
        }
#pragma unroll
        for (int o = 16; o; o >>= 1) acc += __shfl_down_sync(0xFFFFFFFFu, acc, o);
        if (lane == 0) sc[s] = acc;
    }
    __syncthreads();

    if (tx == 0) {
        float mx = sc[0];
        for (int s = 1; s < SS; ++s) mx = fmaxf(mx, sc[s]);
        float sum = 0.f;
        for (int s = 0; s < SS; ++s) { float e = expf(sc[s] - mx); sc[s] = e; sum += e; }
        float inv = 1.f / sum;
        for (int s = 0; s < SS; ++s) sc[s] *= inv;
    }
    __syncthreads();

    if (tx < SS) attn[b * SS + tx] = sc[tx];

    for (int k = tx; k < HH; k += 256) {
        float acc = 0.f;
#pragma unroll 8
        for (int s = 0; s < SS; ++s)
            acc += sc[s] * ctx[((size_t)s * BB + b) * HH + k];
        wc[(size_t)b * HH + k] = acc;
    }
}

__global__ void init_k(const float* __restrict__ h0, const float* __restrict__ c0) {
    int i = blockIdx.x * 256 + threadIdx.x;
    if (i < LL * BB * HH) {
        g_hbuf[0][i] = h0[i];
        g_c[i] = c0[i];
    }
}

__global__ void final_k(float* __restrict__ hf, float* __restrict__ cf,
                        float* __restrict__ at) {
    int i = blockIdx.x * 256 + threadIdx.x;
    if (i < LL * BB * HH) {
        hf[i] = g_hbuf[0][i];  // T=64 even -> final state lives in buffer 0
        cf[i] = g_c[i];
    }
    if (i < BB * SS) at[i] = g_attn[i];
}

extern "C" void kernel_launch(void* const* d_in, const int* in_sizes, int n_in,
                              void* d_out, int out_size) {
    (void)in_sizes; (void)n_in; (void)out_size;
    const int*   inp   = (const int*)d_in[0];
    const float* h0    = (const float*)d_in[1];
    const float* c0    = (const float*)d_in[2];
    const float* ctx   = (const float*)d_in[3];
    const float* emb   = (const float*)d_in[4];
    const float* w_ih  = (const float*)d_in[5];
    const float* w_hh  = (const float*)d_in[6];
    const float* b_ih  = (const float*)d_in[7];
    const float* b_hh  = (const float*)d_in[8];
    const float* w_in  = (const float*)d_in[9];
    const float* w_out = (const float*)d_in[10];

    float* out  = (float*)d_out;
    float* outs = out;
    float* hf   = out + (size_t)TT * BB * HH;
    float* cf   = hf + LL * BB * HH;
    float* at   = cf + LL * BB * HH;

    float *X0, *hbuf, *cS, *q, *wc, *attn;
    cudaGetSymbolAddress((void**)&X0, g_X0);
    cudaGetSymbolAddress((void**)&hbuf, g_hbuf);
    cudaGetSymbolAddress((void**)&cS, g_c);
    cudaGetSymbolAddress((void**)&q, g_q);
    cudaGetSymbolAddress((void**)&wc, g_wc);
    cudaGetSymbolAddress((void**)&attn, g_attn);

    init_k<<<512, 256>>>(h0, c0);

    // Precompute X0[t*B+b, :] = emb[input] @ w_ih[0]^T + b_ih[0] + b_hh[0]
    gemm_k<0, true, false><<<dim3(128, 64), 256>>>(
        emb, w_ih, nullptr, nullptr, 1024, inp,
        nullptr, b_ih, b_hh, X0, 4096, nullptr, nullptr);

    const int LBH = LL * BB * HH;
    for (int t = 0; t < TT; ++t) {
        int rb = t & 1, wb = rb ^ 1;
        float* hR = hbuf + (size_t)rb * LBH;
        float* hW = hbuf + (size_t)wb * LBH;

        // layer 0: gates = X0[t] + h0_old @ w_hh[0]^T ; fused cell
        gemm_k<2, false, false><<<128, 256>>>(
            hR, w_hh, nullptr, nullptr, 1024, nullptr,
            X0 + (size_t)t * BB * 4 * HH, nullptr, nullptr,
            nullptr, 0, cS, hW);

        // layer 1: gates = h0_new @ w_ih[1]^T + h1_old @ w_hh[1]^T + biases ; fused cell
        gemm_k<2, false, true><<<128, 256>>>(
            hW, w_ih + (size_t)4 * HH * HH,
            hR + BB * HH, w_hh + (size_t)4 * HH * HH, 1024, nullptr,
            nullptr, b_ih + 4 * HH, b_hh + 4 * HH,
            nullptr, 0, cS + BB * HH, hW + BB * HH);

        // q = h1_new @ w_in^T
        gemm_k<0, false, false><<<32, 256>>>(
            hW + BB * HH, w_in, nullptr, nullptr, 1024, nullptr,
            nullptr, nullptr, nullptr, q, 1024, nullptr, nullptr);

        attn_k<<<64, 256>>>(q, ctx, wc, attn);

        // out[t] = tanh(wc @ w_out[:, :H]^T + h1_new @ w_out[:, H:]^T)
        gemm_k<1, false, true><<<32, 256>>>(
            wc, w_out, hW + BB * HH, w_out + HH, 2048, nullptr,
            nullptr, nullptr, nullptr,
            outs + (size_t)t * BB * HH, 1024, nullptr, nullptr);
    }

    final_k<<<512, 256>>>(hf, cf, at);
}

// round 2
// speedup vs baseline: 2.4376x; 2.4376x over previous
#include <cuda_runtime.h>
#include <cstdint>

// Decoder: 2-layer LSTM + Luong attention. T=B=S=64, H=E=1024, L=2.
// Software-pipelined: one kernel launch per step carrying
//   [L1(t), out-gemm(t-4)... ] staggered segments; see schedule in host code.

#define TT 64
#define BB 64
#define SS 64
#define HH 1024

typedef unsigned long long ull;

__device__ __forceinline__ void fma2(ull &d, ull a, ull b) {
    asm volatile("fma.rn.f32x2 %0, %1, %2, %0;" : "+l"(d) : "l"(a), "l"(b));
}
__device__ __forceinline__ ull dup2(float x) {
    ull r;
    asm("mov.b64 %0, {%1, %1};" : "=l"(r) : "r"(__float_as_uint(x)));
    return r;
}
__device__ __forceinline__ float2 unpk(ull v) {
    float2 f;
    f.x = __uint_as_float((unsigned)v);
    f.y = __uint_as_float((unsigned)(v >> 32));
    return f;
}
__device__ __forceinline__ float sigm_(float x) { return 1.f / (1.f + expf(-x)); }

// ---------------- scratch ----------------
__device__ float g_X0[(size_t)TT * BB * 4 * HH];  // x@w_ih0^T + b_ih0 + b_hh0
__device__ float g_h0[2][BB * HH];
__device__ float g_h1[4][BB * HH];
__device__ float g_c0[BB * HH];
__device__ float g_c1[BB * HH];
__device__ float g_q[2][BB * HH];
__device__ float g_wc[2][BB * HH];
__device__ float g_attn[BB * SS];

#define SM_BYTES 25600
// smem layout: As[2][16][68] floats (8704B) | Ws[2][16][66] ull (16896B)
// epilogue reuses the whole region as Cs[64][66] floats (16896B)

// ============================================================
// 64(M) x 64(N) x K GEMM core. W row-major [.,ldW], C = A @ W^T.
// GATE: W-row remap for fused LSTM gates (cols = 4 gates x 16 units).
// PAIR2: sum of two GEMMs (A1@W1^T + A2@W2^T), K=2048 total.
// GATHER: A rows via embedding index.
// ============================================================
template <bool PAIR2, bool GATE, bool GATHER>
__device__ __forceinline__ void gemm64(
    const float* __restrict__ A1, const float* __restrict__ A2,
    const float* __restrict__ W1, const float* __restrict__ W2,
    int ldW, int nblk, int mbase, const int* __restrict__ gidx,
    char* smraw, ull acc[2][4])
{
    float (*As)[16][68] = (float (*)[16][68])smraw;
    ull   (*Ws)[16][66] = (ull (*)[16][66])(smraw + 8704);

    const int tx  = threadIdx.x;
    const int ar  = tx >> 2, ak = (tx & 3) << 2;   // A fill: row, k-offset
    const int wrl = tx >> 2, wk = (tx & 3) << 2;   // W fill: local row, k-offset
    const int m0  = (tx & 15) << 2;                // compute: 4 rows
    const int n0  = (tx >> 4) << 2;                // compute: 4 cols

    const int wr = GATE ? ((wrl >> 4) * HH + nblk * 16 + (wrl & 15))
                        : (nblk * 64 + wrl);
    const float* Ar1 = GATHER ? A1 + (size_t)gidx[mbase + ar] * HH
                              : A1 + (size_t)(mbase + ar) * HH;
    const float* Ar2 = PAIR2 ? A2 + (size_t)ar * HH : nullptr;
    const float* Wr1 = W1 + (size_t)wr * ldW;
    const float* Wr2 = PAIR2 ? W2 + (size_t)wr * ldW : nullptr;

    float4 av = *(const float4*)(Ar1 + ak);
    float4 wv = *(const float4*)(Wr1 + wk);

    const int NT = PAIR2 ? 128 : 64;

#define TILE_STEP(BUF, KT)                                                     \
    {                                                                          \
        As[BUF][ak + 0][ar] = av.x; As[BUF][ak + 1][ar] = av.y;                \
        As[BUF][ak + 2][ar] = av.z; As[BUF][ak + 3][ar] = av.w;                \
        Ws[BUF][wk + 0][wrl] = dup2(wv.x); Ws[BUF][wk + 1][wrl] = dup2(wv.y);  \
        Ws[BUF][wk + 2][wrl] = dup2(wv.z); Ws[BUF][wk + 3][wrl] = dup2(wv.w);  \
        __syncthreads();                                                       \
        int kn = (KT) + 1;                                                     \
        if (kn < NT) {                                                         \
            const float *Ap, *Wp; int kk;                                      \
            if (PAIR2 && kn >= 64) { Ap = Ar2; Wp = Wr2; kk = (kn - 64) * 16; }\
            else                   { Ap = Ar1; Wp = Wr1; kk = kn * 16; }       \
            av = *(const float4*)(Ap + kk + ak);                               \
            wv = *(const float4*)(Wp + kk + wk);                               \
        }                                                                      \
        _Pragma("unroll")                                                      \
        for (int k = 0; k < 16; ++k) {                                         \
            ulonglong2 aa  = *(const ulonglong2*)&As[BUF][k][m0];              \
            ulonglong2 w01 = *(const ulonglong2*)&Ws[BUF][k][n0];              \
            ulonglong2 w23 = *(const ulonglong2*)&Ws[BUF][k][n0 + 2];          \
            fma2(acc[0][0], aa.x, w01.x); fma2(acc[1][0], aa.y, w01.x);        \
            fma2(acc[0][1], aa.x, w01.y); fma2(acc[1][1], aa.y, w01.y);        \
            fma2(acc[0][2], aa.x, w23.x); fma2(acc[1][2], aa.y, w23.x);        \
            fma2(acc[0][3], aa.x, w23.y); fma2(acc[1][3], aa.y, w23.y);        \
        }                                                                      \
    }

    for (int kt = 0; kt < NT; kt += 2) {
        TILE_STEP(0, kt)
        TILE_STEP(1, kt + 1)
    }
#undef TILE_STEP
}

// Stage accumulators to smem as Cs[col][row] (pitch 66).
__device__ __forceinline__ void stage_acc(char* smraw, ull acc[2][4]) {
    float* Cs = (float*)smraw;
    const int tx = threadIdx.x;
    const int m0 = (tx & 15) << 2, n0 = (tx >> 4) << 2;
    __syncthreads();  // done reading As/Ws
#pragma unroll
    for (int j = 0; j < 4; ++j) {
        *(float2*)&Cs[(n0 + j) * 66 + m0]     = unpk(acc[0][j]);
        *(float2*)&Cs[(n0 + j) * 66 + m0 + 2] = unpk(acc[1][j]);
    }
    __syncthreads();
}

// Fused LSTM cell epilogue: cols are (gate g)*16 + jj for 16 hidden units.
__device__ __forceinline__ void cell_epi(
    char* smraw, int nblk,
    const float* __restrict__ add,    // X0 slice [B,4096] or null
    const float* __restrict__ B1, const float* __restrict__ B2,
    float* __restrict__ cSt, float* __restrict__ hOut)
{
    float* Cs = (float*)smraw;
    const int tx = threadIdx.x;
#pragma unroll
    for (int it = 0; it < 4; ++it) {
        int idx = tx + it * 256;
        int b = idx & 63, jj = idx >> 6;
        int jg = nblk * 16 + jj;
        float gi = Cs[jj * 66 + b];
        float gf = Cs[(16 + jj) * 66 + b];
        float gg = Cs[(32 + jj) * 66 + b];
        float go = Cs[(48 + jj) * 66 + b];
        if (add) {
            const float* ac = add + (size_t)b * 4096 + jg;
            gi += ac[0]; gf += ac[1024]; gg += ac[2048]; go += ac[3072];
        }
        if (B1) {
            gi += B1[jg] + B2[jg];
            gf += B1[1024 + jg] + B2[1024 + jg];
            gg += B1[2048 + jg] + B2[2048 + jg];
            go += B1[3072 + jg] + B2[3072 + jg];
        }
        float ii = sigm_(gi), ff = sigm_(gf);
        float g = tanhf(gg), oo = sigm_(go);
        float c = ff * cSt[b * HH + jg] + ii * g;
        cSt[b * HH + jg] = c;
        hOut[b * HH + jg] = oo * tanhf(c);
    }
}

// Plain store epilogue (optional bias / tanh), coalesced.
template <bool BIAS, bool TANH>
__device__ __forceinline__ void store_epi(
    char* smraw, int nbase, int mbase,
    const float* __restrict__ B1, const float* __restrict__ B2,
    float* __restrict__ C, int ldC)
{
    float* Cs = (float*)smraw;
    const int tx = threadIdx.x;
#pragma unroll
    for (int it = 0; it < 16; ++it) {
        int idx = tx + it * 256;
        int row = idx >> 6, col = idx & 63;
        float v = Cs[col * 66 + row];
        int cg = nbase + col;
        if (BIAS) v += B1[cg] + B2[cg];
        if (TANH) v = tanhf(v);
        C[(size_t)(mbase + row) * ldC + cg] = v;
    }
}

// ---------------- step kernel: fused pipeline segments ----------------
struct StepP {
    int nL1, nOut, nL0, nQ, nAt;
    // L1
    const float *l1A1, *l1A2, *l1W1, *l1W2, *l1B1, *l1B2;
    float *l1C, *l1H;
    // OUT
    const float *oA1, *oA2, *oW;
    float *oOut;
    // L0
    const float *l0A1, *l0W, *l0Add;
    float *l0C, *l0H;
    // Q
    const float *qA, *qW;
    float *qOut;
    // ATTN
    const float *atQ, *atCtx;
    float *atWc, *atP;
};

__global__ __launch_bounds__(256, 2) void step_k(StepP p) {
    __shared__ __align__(16) char smraw[SM_BYTES];
    const int bid = blockIdx.x;
    const int r0 = p.nL1, r1 = r0 + p.nOut, r2 = r1 + p.nL0, r3 = r2 + p.nQ;
    ull acc[2][4] = {{0, 0, 0, 0}, {0, 0, 0, 0}};

    if (bid < r0) {                       // L1: gates then cell
        int nblk = bid;
        gemm64<true, true, false>(p.l1A1, p.l1A2, p.l1W1, p.l1W2, HH,
                                  nblk, 0, nullptr, smraw, acc);
        stage_acc(smraw, acc);
        cell_epi(smraw, nblk, nullptr, p.l1B1, p.l1B2, p.l1C, p.l1H);
    } else if (bid < r1) {                // OUT: tanh([wc,h1]@w_out^T)
        int nblk = bid - r0;
        gemm64<true, false, false>(p.oA1, p.oA2, p.oW, p.oW + HH, 2 * HH,
                                   nblk, 0, nullptr, smraw, acc);
        stage_acc(smraw, acc);
        store_epi<false, true>(smraw, nblk * 64, 0, nullptr, nullptr, p.oOut, HH);
    } else if (bid < r2) {                // L0: gates (+X0) then cell
        int nblk = bid - r1;
        gemm64<false, true, false>(p.l0A1, nullptr, p.l0W, nullptr, HH,
                                   nblk, 0, nullptr, smraw, acc);
        stage_acc(smraw, acc);
        cell_epi(smraw, nblk, p.l0Add, nullptr, nullptr, p.l0C, p.l0H);
    } else if (bid < r3) {                // Q: h1 @ w_in^T
        int nblk = bid - r2;
        gemm64<false, false, false>(p.qA, nullptr, p.qW, nullptr, HH,
                                    nblk, 0, nullptr, smraw, acc);
        stage_acc(smraw, acc);
        store_epi<false, false>(smraw, nblk * 64, 0, nullptr, nullptr, p.qOut, HH);
    } else {                              // ATTN: scores/softmax/wc for one b
        int b = bid - r3;
        float* qs = (float*)smraw;        // 1024 floats
        float* sc = qs + 1024;            // 64 floats
        const int tx = threadIdx.x;
        *(float4*)&qs[tx * 4] = *(const float4*)&p.atQ[(size_t)b * HH + tx * 4];
        __syncthreads();
        const int wid = tx >> 5, lane = tx & 31;
        for (int s = wid; s < SS; s += 8) {
            const float* cp = p.atCtx + ((size_t)s * BB + b) * HH;
            float a = 0.f;
#pragma unroll
            for (int i = 0; i < 8; ++i) {
                float4 c4 = *(const float4*)(cp + i * 128 + lane * 4);
                float4 q4 = *(const float4*)&qs[i * 128 + lane * 4];
                a += c4.x * q4.x + c4.y * q4.y + c4.z * q4.z + c4.w * q4.w;
            }
#pragma unroll
            for (int o = 16; o; o >>= 1) a += __shfl_down_sync(0xFFFFFFFFu, a, o);
            if (lane == 0) sc[s] = a;
        }
        __syncthreads();
        if (tx == 0) {
            float mx = sc[0];
            for (int s = 1; s < SS; ++s) mx = fmaxf(mx, sc[s]);
            float sum = 0.f;
            for (int s = 0; s < SS; ++s) { float e = expf(sc[s] - mx); sc[s] = e; sum += e; }
            float inv = 1.f / sum;
            for (int s = 0; s < SS; ++s) sc[s] *= inv;
        }
        __syncthreads();
        if (tx < SS) p.atP[b * SS + tx] = sc[tx];
        for (int k = tx; k < HH; k += 256) {
            float a = 0.f;
#pragma unroll 8
            for (int s = 0; s < SS; ++s)
                a += sc[s] * p.atCtx[((size_t)s * BB + b) * HH + k];
            p.atWc[(size_t)b * HH + k] = a;
        }
    }
}

// ---------------- precompute: X0 = emb[input] @ w_ih0^T + biases ----------------
__global__ __launch_bounds__(256, 2) void pre_k(
    const int* __restrict__ gidx, const float* __restrict__ emb,
    const float* __restrict__ W, const float* __restrict__ B1,
    const float* __restrict__ B2, float* __restrict__ X0)
{
    __shared__ __align__(16) char smraw[SM_BYTES];
    ull acc[2][4] = {{0, 0, 0, 0}, {0, 0, 0, 0}};
    int nblk = blockIdx.x, mbase = blockIdx.y * 64;
    gemm64<false, false, true>(emb, nullptr, W, nullptr, HH,
                               nblk, mbase, gidx, smraw, acc);
    stage_acc(smraw, acc);
    store_epi<true, false>(smraw, nblk * 64, mbase, B1, B2, X0, 4 * HH);
}

__global__ void init_k(const float* __restrict__ h0, const float* __restrict__ c0) {
    int i = blockIdx.x * 256 + threadIdx.x;
    if (i < BB * HH) {
        g_h0[1][i] = h0[i];                 // h0(-1), slot (-1)&1 = 1
        g_h1[3][i] = h0[BB * HH + i];       // h1(-1), slot (-1)&3 = 3
        g_c0[i] = c0[i];
        g_c1[i] = c0[BB * HH + i];
    }
}

__global__ void final_k(float* __restrict__ hf, float* __restrict__ cf,
                        float* __restrict__ at) {
    int i = blockIdx.x * 256 + threadIdx.x;
    if (i < BB * HH) {
        hf[i] = g_h0[1][i];                 // h0(63): 63&1 = 1
        hf[BB * HH + i] = g_h1[3][i];       // h1(63): 63&3 = 3
        cf[i] = g_c0[i];
        cf[BB * HH + i] = g_c1[i];
    }
    if (i < BB * SS) at[i] = g_attn[i];
}

extern "C" void kernel_launch(void* const* d_in, const int* in_sizes, int n_in,
                              void* d_out, int out_size) {
    (void)in_sizes; (void)n_in; (void)out_size;
    const int*   inp   = (const int*)d_in[0];
    const float* h0    = (const float*)d_in[1];
    const float* c0    = (const float*)d_in[2];
    const float* ctx   = (const float*)d_in[3];
    const float* emb   = (const float*)d_in[4];
    const float* w_ih  = (const float*)d_in[5];
    const float* w_hh  = (const float*)d_in[6];
    const float* b_ih  = (const float*)d_in[7];
    const float* b_hh  = (const float*)d_in[8];
    const float* w_in  = (const float*)d_in[9];
    const float* w_out = (const float*)d_in[10];

    float* out  = (float*)d_out;
    float* outs = out;
    float* hf   = out + (size_t)TT * BB * HH;
    float* cf   = hf + 2 * BB * HH;
    float* at   = cf + 2 * BB * HH;

    float *X0, *H0, *H1, *C0, *C1, *Q, *WC, *AT;
    cudaGetSymbolAddress((void**)&X0, g_X0);
    cudaGetSymbolAddress((void**)&H0, g_h0);
    cudaGetSymbolAddress((void**)&H1, g_h1);
    cudaGetSymbolAddress((void**)&C0, g_c0);
    cudaGetSymbolAddress((void**)&C1, g_c1);
    cudaGetSymbolAddress((void**)&Q,  g_q);
    cudaGetSymbolAddress((void**)&WC, g_wc);
    cudaGetSymbolAddress((void**)&AT, g_attn);
    const int BH = BB * HH;

    init_k<<<256, 256>>>(h0, c0);
    pre_k<<<dim3(64, 64), 256>>>(inp, emb, w_ih, b_ih, b_hh, X0);

    // Pipeline: launch k carries L1(k-1), OUT(k-4), L0(k), Q(k-2), ATTN(k-3).
    for (int k = 0; k <= 67; ++k) {
        StepP p = {};
        int tL1 = k - 1, tL0 = k, tQ = k - 2, tAt = k - 3, tOut = k - 4;
        if (tL1 >= 0 && tL1 < TT) {
            p.nL1 = 64;
            p.l1A1 = H0 + (tL1 & 1) * BH;
            p.l1A2 = H1 + ((tL1 - 1) & 3) * BH;
            p.l1W1 = w_ih + (size_t)4 * HH * HH;
            p.l1W2 = w_hh + (size_t)4 * HH * HH;
            p.l1B1 = b_ih + 4 * HH;
            p.l1B2 = b_hh + 4 * HH;
            p.l1C = C1;
            p.l1H = H1 + (tL1 & 3) * BH;
        }
        if (tOut >= 0 && tOut < TT) {
            p.nOut = 16;
            p.oA1 = WC + (tOut & 1) * BH;
            p.oA2 = H1 + (tOut & 3) * BH;
            p.oW = w_out;
            p.oOut = outs + (size_t)tOut * BH;
        }
        if (tL0 >= 0 && tL0 < TT) {
            p.nL0 = 64;
            p.l0A1 = H0 + ((tL0 + 1) & 1) * BH;
            p.l0W = w_hh;
            p.l0Add = X0 + (size_t)tL0 * BB * 4 * HH;
            p.l0C = C0;
            p.l0H = H0 + (tL0 & 1) * BH;
        }
        if (tQ >= 0 && tQ < TT) {
            p.nQ = 16;
            p.qA = H1 + (tQ & 3) * BH;
            p.qW = w_in;
            p.qOut = Q + (tQ & 1) * BH;
        }
        if (tAt >= 0 && tAt < TT) {
            p.nAt = 64;
            p.atQ = Q + (tAt & 1) * BH;
            p.atCtx = ctx;
            p.atWc = WC + (tAt & 1) * BH;
            p.atP = AT;
        }
        int grid = p.nL1 + p.nOut + p.nL0 + p.nQ + p.nAt;
        if (grid > 0) step_k<<<grid, 256>>>(p);
    }

    final_k<<<512, 256>>>(hf, cf, at);
}